// round 2
// baseline (speedup 1.0000x reference)
#include <cuda_runtime.h>
#include <math.h>

#define NN_MAX 50000
#define NE_MAX 1000000

// ---- device-global scratch (no allocations allowed) ----
__device__ float g_s[NN_MAX];          // scalar feature per node
__device__ float g_v[NN_MAX * 6];      // vector features (2,3) per node
__device__ float g_su[NN_MAX];         // su per node
__device__ float g_vu[NN_MAX * 6];     // vu per node
__device__ float g_agg[NN_MAX * 20];   // 18 used, padded to 20 for alignment
__device__ float g_nhat[NE_MAX * 3];
__device__ float g_radial[NE_MAX * 8];
__device__ float g_mix[NE_MAX * 8];

#define INV_SQRT2 0.70710678118654752f
#define INV_SQRT3 0.57735026918962576f
#define INV_SQRT5 0.44721359549995794f
#define INV_SQRT8 0.35355339059327376f
#define SQRT2_F   1.4142135623730951f
#define C121_F    2.1213203435596424f
#define SQRT3_F   1.7320508075688772f

__device__ __forceinline__ float swishf(float x) {
    return x / (1.0f + __expf(-x));
}

// ---------------------------------------------------------------------------
// init node state from node_features
// ---------------------------------------------------------------------------
__global__ void k_init(const float* __restrict__ nf, int nn) {
    int n = blockIdx.x * blockDim.x + threadIdx.x;
    if (n >= nn) return;
    g_s[n] = nf[n * 7];
#pragma unroll
    for (int i = 0; i < 6; i++) g_v[n * 6 + i] = nf[n * 7 + 1 + i];
}

// ---------------------------------------------------------------------------
// per-edge geometry: nhat + radial basis (8 features)
// ---------------------------------------------------------------------------
__global__ void k_geom(const float* __restrict__ pos,
                       const int* __restrict__ snd,
                       const int* __restrict__ rcv, int ne) {
    int e = blockIdx.x * blockDim.x + threadIdx.x;
    if (e >= ne) return;
    int s = snd[e], r = rcv[e];
    float vx = pos[r * 3 + 0] - pos[s * 3 + 0];
    float vy = pos[r * 3 + 1] - pos[s * 3 + 1];
    float vz = pos[r * 3 + 2] - pos[s * 3 + 2];
    float len = sqrtf(vx * vx + vy * vy + vz * vz);
    float inv = (len == 0.0f) ? 1.0f : (1.0f / len);
    g_nhat[e * 3 + 0] = vx * inv;
    g_nhat[e * 3 + 1] = vy * inv;
    g_nhat[e * 3 + 2] = vz * inv;

    float env = 0.0f;
    if (len < 1.0f) {
        float x = len;
        float x2 = x * x, x3 = x2 * x;
        float x6 = x3 * x3, x7 = x6 * x, x8 = x7 * x;
        env = 1.0f - 28.0f * x6 + 48.0f * x7 - 21.0f * x8;
    }
    float coef = (len == 0.0f) ? 0.0f : (SQRT2_F * env * inv);

    // sin(pi*k*len), k=1..8 via Chebyshev recurrence
    float s1, c1;
    sincospif(len, &s1, &c1);
    float out[8];
    float sm1 = 0.0f, sk = s1;
#pragma unroll
    for (int k = 0; k < 8; k++) {
        out[k] = sk * coef;
        float nx = 2.0f * c1 * sk - sm1;
        sm1 = sk; sk = nx;
    }
    *(float4*)&g_radial[e * 8]     = make_float4(out[0], out[1], out[2], out[3]);
    *(float4*)&g_radial[e * 8 + 4] = make_float4(out[4], out[5], out[6], out[7]);
}

// ---------------------------------------------------------------------------
// radial MLP: mix = (swish(swish(radial@W1/s8)@W2/8)@W3)/8   (per layer)
// Dominant compute: weights in smem (broadcast LDS.128), 4-wide j-blocking.
// ---------------------------------------------------------------------------
__global__ __launch_bounds__(128) void k_mix(const float* __restrict__ W1,
                                             const float* __restrict__ W2,
                                             const float* __restrict__ W3,
                                             int ne) {
    __shared__ float sW1[8 * 64];
    __shared__ float sW2[64 * 64];
    __shared__ float sW3[64 * 8];
    for (int i = threadIdx.x; i < 512; i += blockDim.x) {
        sW1[i] = W1[i];
        sW3[i] = W3[i];
    }
    for (int i = threadIdx.x; i < 4096; i += blockDim.x) sW2[i] = W2[i];
    __syncthreads();

    int e = blockIdx.x * blockDim.x + threadIdx.x;
    if (e >= ne) return;

    float4 ra = *(const float4*)&g_radial[e * 8];
    float4 rb = *(const float4*)&g_radial[e * 8 + 4];
    float r8[8] = {ra.x, ra.y, ra.z, ra.w, rb.x, rb.y, rb.z, rb.w};

    float h1[64];
#pragma unroll
    for (int j = 0; j < 64; j++) {
        float a = 0.0f;
#pragma unroll
        for (int i = 0; i < 8; i++) a = fmaf(r8[i], sW1[i * 64 + j], a);
        h1[j] = swishf(a * INV_SQRT8);
    }

    float mx[8] = {0, 0, 0, 0, 0, 0, 0, 0};
    for (int j = 0; j < 64; j += 4) {
        float a0 = 0.0f, a1 = 0.0f, a2 = 0.0f, a3 = 0.0f;
#pragma unroll
        for (int i = 0; i < 64; i++) {
            const float4 w = *(const float4*)&sW2[i * 64 + j];
            a0 = fmaf(h1[i], w.x, a0);
            a1 = fmaf(h1[i], w.y, a1);
            a2 = fmaf(h1[i], w.z, a2);
            a3 = fmaf(h1[i], w.w, a3);
        }
        float h20 = swishf(a0 * 0.125f);
        float h21 = swishf(a1 * 0.125f);
        float h22 = swishf(a2 * 0.125f);
        float h23 = swishf(a3 * 0.125f);
#pragma unroll
        for (int k = 0; k < 8; k++) {
            mx[k] = fmaf(h20, sW3[(j + 0) * 8 + k], mx[k]);
            mx[k] = fmaf(h21, sW3[(j + 1) * 8 + k], mx[k]);
            mx[k] = fmaf(h22, sW3[(j + 2) * 8 + k], mx[k]);
            mx[k] = fmaf(h23, sW3[(j + 3) * 8 + k], mx[k]);
        }
    }
#pragma unroll
    for (int k = 0; k < 8; k++) mx[k] *= 0.125f;
    *(float4*)&g_mix[e * 8]     = make_float4(mx[0], mx[1], mx[2], mx[3]);
    *(float4*)&g_mix[e * 8 + 4] = make_float4(mx[4], mx[5], mx[6], mx[7]);
}

// ---------------------------------------------------------------------------
// node pre: su/vu from current s/v, zero agg
// ---------------------------------------------------------------------------
__global__ void k_node_pre(const float* __restrict__ Wus,
                           const float* __restrict__ Wuv, int nn) {
    int n = blockIdx.x * blockDim.x + threadIdx.x;
    if (n >= nn) return;
    float s = g_s[n];
    g_su[n] = s * Wus[0];
    float w00 = Wuv[0], w01 = Wuv[1], w10 = Wuv[2], w11 = Wuv[3];  // [m][k]
#pragma unroll
    for (int c = 0; c < 3; c++) {
        float a = g_v[n * 6 + c], b = g_v[n * 6 + 3 + c];
        g_vu[n * 6 + c]     = (a * w00 + b * w10) * INV_SQRT2;  // k=0
        g_vu[n * 6 + 3 + c] = (a * w01 + b * w11) * INV_SQRT2;  // k=1
    }
#pragma unroll
    for (int i = 0; i < 20; i++) g_agg[n * 20 + i] = 0.0f;
}

// ---------------------------------------------------------------------------
// per-edge message + scatter (atomicAdd into L2-resident agg)
// agg layout: [0..2]=msg_s, [3..5]=ve0, [6..8]=ve1, [9..11]=pc0,
//             [12..14]=pc1, [15..17]=pb
// ---------------------------------------------------------------------------
__global__ void k_edge(const int* __restrict__ snd,
                       const int* __restrict__ rcv, int ne) {
    int e = blockIdx.x * blockDim.x + threadIdx.x;
    if (e >= ne) return;
    int s = snd[e], r = rcv[e];
    float nx = g_nhat[e * 3 + 0];
    float ny = g_nhat[e * 3 + 1];
    float nz = g_nhat[e * 3 + 2];
    float4 m0 = *(const float4*)&g_mix[e * 8];      // mix0..3
    float4 m1 = *(const float4*)&g_mix[e * 8 + 4];  // mix4..7

    float se  = g_su[s];
    float v0x = g_vu[s * 6 + 0], v0y = g_vu[s * 6 + 1], v0z = g_vu[s * 6 + 2];
    float v1x = g_vu[s * 6 + 3], v1y = g_vu[s * 6 + 4], v1z = g_vu[s * 6 + 5];

    float d0 = v0x * nx + v0y * ny + v0z * nz;
    float d1 = v1x * nx + v1y * ny + v1z * nz;

    float* base = &g_agg[r * 20];
    // msg_s
    atomicAdd(base + 0, se * m0.x);
    atomicAdd(base + 1, d0 * m0.y);
    atomicAdd(base + 2, d1 * m0.z);
    // row0 = ve0 * mix3
    atomicAdd(base + 3, v0x * m0.w);
    atomicAdd(base + 4, v0y * m0.w);
    atomicAdd(base + 5, v0z * m0.w);
    // row1 = ve1 * mix4
    atomicAdd(base + 6, v1x * m1.x);
    atomicAdd(base + 7, v1y * m1.x);
    atomicAdd(base + 8, v1z * m1.x);
    // pc0 = C121*(d0*n - v0/3) * mix5
    const float third = 1.0f / 3.0f;
    atomicAdd(base + 9,  C121_F * (d0 * nx - v0x * third) * m1.y);
    atomicAdd(base + 10, C121_F * (d0 * ny - v0y * third) * m1.y);
    atomicAdd(base + 11, C121_F * (d0 * nz - v0z * third) * m1.y);
    // pc1 = C121*(d1*n - v1/3) * mix6
    atomicAdd(base + 12, C121_F * (d1 * nx - v1x * third) * m1.z);
    atomicAdd(base + 13, C121_F * (d1 * ny - v1y * third) * m1.z);
    atomicAdd(base + 14, C121_F * (d1 * nz - v1z * third) * m1.z);
    // pb = SQRT3*se*n * mix7
    atomicAdd(base + 15, SQRT3_F * se * nx * m1.w);
    atomicAdd(base + 16, SQRT3_F * se * ny * m1.w);
    atomicAdd(base + 17, SQRT3_F * se * nz * m1.w);
}

// ---------------------------------------------------------------------------
// node post: downmix agg, residual, gates, update s/v (and write output)
// ---------------------------------------------------------------------------
__global__ void k_node_post(const float* __restrict__ Wss,
                            const float* __restrict__ Wsv,
                            const float* __restrict__ Wds,
                            const float* __restrict__ Wdv,
                            float* __restrict__ out, int write_out, int nn) {
    int n = blockIdx.x * blockDim.x + threadIdx.x;
    if (n >= nn) return;
    float s = g_s[n];
    float v[6];
#pragma unroll
    for (int i = 0; i < 6; i++) v[i] = g_v[n * 6 + i];
    float agg[18];
#pragma unroll
    for (int i = 0; i < 18; i++) agg[i] = g_agg[n * 20 + i];

    float st[3];
#pragma unroll
    for (int k = 0; k < 3; k++) {
        float sd = (agg[0] * Wds[0 * 3 + k] + agg[1] * Wds[1 * 3 + k] +
                    agg[2] * Wds[2 * 3 + k]) * INV_SQRT3;
        st[k] = sd + s * Wss[k];
    }
    float vt[6];
#pragma unroll
    for (int k = 0; k < 2; k++) {
#pragma unroll
        for (int c = 0; c < 3; c++) {
            float vd = 0.0f;
#pragma unroll
            for (int m = 0; m < 5; m++) vd = fmaf(agg[3 + m * 3 + c], Wdv[m * 2 + k], vd);
            vd *= INV_SQRT5;
            float vsc = (v[c] * Wsv[0 * 2 + k] + v[3 + c] * Wsv[1 * 2 + k]) * INV_SQRT2;
            vt[k * 3 + c] = vd + vsc;
        }
    }
    float ns = swishf(st[0]);
    float g1 = swishf(st[1]);
    float g2 = swishf(st[2]);
    g_s[n] = ns;
#pragma unroll
    for (int c = 0; c < 3; c++) {
        float nv0 = vt[c] * g1;
        float nv1 = vt[3 + c] * g2;
        g_v[n * 6 + c]     = nv0;
        g_v[n * 6 + 3 + c] = nv1;
        if (write_out) out[n * 3 + c] = nv0;
    }
}

// ---------------------------------------------------------------------------
// launch
// ---------------------------------------------------------------------------
extern "C" void kernel_launch(void* const* d_in, const int* in_sizes, int n_in,
                              void* d_out, int out_size) {
    const float* pos = (const float*)d_in[0];
    const float* nf  = (const float*)d_in[1];
    const int* snd   = (const int*)d_in[2];
    const int* rcv   = (const int*)d_in[3];
    const float* Wss = (const float*)d_in[4];
    const float* Wsv = (const float*)d_in[5];
    const float* Wus = (const float*)d_in[6];
    const float* Wuv = (const float*)d_in[7];
    const float* W1  = (const float*)d_in[8];
    const float* W2  = (const float*)d_in[9];
    const float* W3  = (const float*)d_in[10];
    const float* Wds = (const float*)d_in[11];
    const float* Wdv = (const float*)d_in[12];
    float* out = (float*)d_out;

    int ne = in_sizes[2];
    int nn = in_sizes[0] / 3;

    int nb_n = (nn + 255) / 256;
    int nb_e = (ne + 255) / 256;
    int nb_m = (ne + 127) / 128;

    k_init<<<nb_n, 256>>>(nf, nn);
    k_geom<<<nb_e, 256>>>(pos, snd, rcv, ne);

    for (int l = 0; l < 3; l++) {
        k_node_pre<<<nb_n, 256>>>(Wus + l * 1, Wuv + l * 4, nn);
        k_mix<<<nb_m, 128>>>(W1 + l * 512, W2 + l * 4096, W3 + l * 512, ne);
        k_edge<<<nb_e, 256>>>(snd, rcv, ne);
        k_node_post<<<nb_n, 256>>>(Wss + l * 3, Wsv + l * 4, Wds + l * 9,
                                   Wdv + l * 10, out, (l == 2) ? 1 : 0, nn);
    }
}